// round 14
// baseline (speedup 1.0000x reference)
#include <cuda_runtime.h>
#include <cuda_fp16.h>
#include <math.h>
#include <stdint.h>

#define Bb   8
#define Ss   1024
#define Dd   768
#define Hh   12
#define HDd  64
#define HIDh 3072
#define Mm   (Bb*Ss)   // 8192
#define NPERS 456      // 152 SMs * 3 CTAs/SM

// ---------------- scratch (device globals; no allocs allowed) ----------------
__device__ __half g_q   [(size_t)Mm*Dd];
__device__ __half g_k   [(size_t)Mm*Dd];
__device__ __half g_v   [(size_t)Mm*Dd];
__device__ __half g_ln2 [(size_t)Mm*Dd];
__device__ __half g_h1  [(size_t)Mm*HIDh];
__device__ __half g_xc  [(size_t)Mm*Dd];
__device__ __half g_wq  [(size_t)Dd*Dd];      // [K,N] original layout, fp16
__device__ __half g_wk  [(size_t)Dd*Dd];
__device__ __half g_wv  [(size_t)Dd*Dd];
__device__ __half g_win [(size_t)Dd*HIDh];
__device__ __half g_wout[(size_t)HIDh*Dd];
__device__ float g_ctx[(size_t)Mm*Dd];
__device__ float g_y  [(size_t)Mm*Dd];

__device__ __forceinline__ float gelu_exact(float x) {
    return 0.5f * x * (1.0f + erff(x * 0.70710678118654752f));
}
__device__ __forceinline__ void cp_async16(uint32_t saddr, const void* gaddr) {
    asm volatile("cp.async.cg.shared.global [%0], [%1], 16;\n" :: "r"(saddr), "l"(gaddr));
}
__device__ __forceinline__ uint32_t smem_u32(const void* p) {
    uint32_t a;
    asm("{ .reg .u64 t; cvta.to.shared.u64 t, %1; cvt.u32.u64 %0, t; }"
        : "=r"(a) : "l"(p));
    return a;
}
__device__ __forceinline__ void ldsm_x4(uint32_t& r0, uint32_t& r1,
                                        uint32_t& r2, uint32_t& r3, uint32_t a) {
    asm volatile("ldmatrix.sync.aligned.m8n8.x4.shared.b16 {%0,%1,%2,%3}, [%4];"
                 : "=r"(r0), "=r"(r1), "=r"(r2), "=r"(r3) : "r"(a));
}
__device__ __forceinline__ void ldsm_x4_t(uint32_t& r0, uint32_t& r1,
                                          uint32_t& r2, uint32_t& r3, uint32_t a) {
    asm volatile("ldmatrix.sync.aligned.m8n8.x4.trans.shared.b16 {%0,%1,%2,%3}, [%4];"
                 : "=r"(r0), "=r"(r1), "=r"(r2), "=r"(r3) : "r"(a));
}
__device__ __forceinline__ void mma_f16(float* c, const uint32_t* a,
                                        uint32_t b0, uint32_t b1) {
    asm volatile(
        "mma.sync.aligned.m16n8k16.row.col.f32.f16.f16.f32 "
        "{%0,%1,%2,%3},{%4,%5,%6,%7},{%8,%9},{%0,%1,%2,%3};"
        : "+f"(c[0]), "+f"(c[1]), "+f"(c[2]), "+f"(c[3])
        : "r"(a[0]), "r"(a[1]), "r"(a[2]), "r"(a[3]), "r"(b0), "r"(b1));
}
__device__ __forceinline__ uint32_t pack_h2(float a, float b) {
    __half2 h = __floats2half2_rn(a, b);
    return *(uint32_t*)&h;
}

// ---------------- prep kernels ----------------------------------------------
__global__ __launch_bounds__(256) void prep_x(const float* __restrict__ src, int n4)
{
    int i = blockIdx.x * 256 + threadIdx.x;
    if (i < n4) {
        float4 f = ((const float4*)src)[i];
        uint2 u;
        u.x = pack_h2(f.x, f.y);
        u.y = pack_h2(f.z, f.w);
        ((uint2*)g_xc)[i] = u;
    }
}

// one launch, z = 0..4 : wq wk wv win wout
__global__ __launch_bounds__(256) void prep_w5(const float* __restrict__ s0,
                                               const float* __restrict__ s1,
                                               const float* __restrict__ s2,
                                               const float* __restrict__ s3,
                                               const float* __restrict__ s4)
{
    const int id = blockIdx.z;
    const float* src = id == 0 ? s0 : id == 1 ? s1 : id == 2 ? s2
                     : id == 3 ? s3 : s4;
    __half* dst = id == 0 ? g_wq : id == 1 ? g_wk : id == 2 ? g_wv
                : id == 3 ? g_win : g_wout;
    const int n4 = (id < 3) ? (Dd*Dd/4) : (Dd*HIDh/4);
    int i = blockIdx.x * 256 + threadIdx.x;
    if (i < n4) {
        float4 f = ((const float4*)src)[i];
        uint2 u;
        u.x = pack_h2(f.x, f.y);
        u.y = pack_h2(f.z, f.w);
        ((uint2*)dst)[i] = u;
    }
}

// =====================================================================
// FP16 GEMM v8 (persistent tiles): CTA 128x128, 4 warps, warp 64x64,
// BK=64, 2-stage double buffer, one barrier per k-tile; each CTA loops
// over tiles with stride gridDim.x (x-major for L2 A-reuse).
// A [M,K] K-major (ldsm), B [K,N] K-major (ldsm.trans).
// =====================================================================
#define HSTR 72
#define BSTR 136
#define A_STG_B (128*HSTR*2)        // 18432
#define B_STG_B (64*BSTR*2)         // 17408
#define GSMEM (2*A_STG_B + 2*B_STG_B)  // 71680

template<int MODE>
__global__ __launch_bounds__(128) void gemm_fp16(
    const float* __restrict__ bias0, const float* __restrict__ bias1,
    const float* __restrict__ bias2, float* __restrict__ Cout,
    int N, int K)
{
    extern __shared__ __half smem[];

    const int tid  = threadIdx.x;
    const int lane = tid & 31;
    const int warp = tid >> 5;
    const int warpM = warp & 1;
    const int warpN = warp >> 1;
    const int quad = lane >> 2;
    const int tkid = lane & 3;

    uint32_t sA = smem_u32(smem);
    uint32_t sB = sA + 2 * A_STG_B;

    const int a_r = lane & 15;
    const int a_c = (lane >> 4) * 8;
    const int b_tr = (((lane >> 3) & 1) * 8) + (lane & 7);
    const int b_tc = (lane >> 4) * 8;

    const int tilesX = N >> 7;
    const int tilesY = Mm >> 7;
    const int tilesXY = tilesX * tilesY;
    const int ntiles = tilesXY * ((MODE == 0) ? 3 : 1);
    const int KT = K / 64;

    const __half* A = (MODE == 0) ? g_xc : (MODE == 1 ? g_ln2 : g_h1);

    for (int tile = blockIdx.x; tile < ntiles; tile += gridDim.x) {
        int which = 0, rem = tile;
        if (MODE == 0) { which = tile / tilesXY; rem = tile - which * tilesXY; }
        const int m0 = (rem / tilesX) * 128;
        const int n0 = (rem % tilesX) * 128;

        const __half* Bw = (MODE == 0)
            ? (which == 0 ? g_wq : (which == 1 ? g_wk : g_wv))
            : (MODE == 1 ? g_win : g_wout);
        const float* bias = (MODE == 0)
            ? (which == 0 ? bias0 : (which == 1 ? bias1 : bias2)) : bias0;

        auto load_tile = [&](int kt, int buf) {
            const int k0 = kt * 64;
            #pragma unroll
            for (int i = 0; i < 8; i++) {
                int idx = tid + i * 128;
                int row = idx >> 3;
                int c8  = (idx & 7) * 8;
                cp_async16(sA + buf * A_STG_B + (row * HSTR + c8) * 2,
                           A + (size_t)(m0 + row) * K + k0 + c8);
            }
            #pragma unroll
            for (int i = 0; i < 8; i++) {
                int idx = tid + i * 128;
                int row = idx >> 4;
                int c8  = (idx & 15) * 8;
                cp_async16(sB + buf * B_STG_B + (row * BSTR + c8) * 2,
                           Bw + (size_t)(k0 + row) * N + n0 + c8);
            }
            asm volatile("cp.async.commit_group;\n");
        };

        // protect smem from previous tile's in-flight reads
        __syncthreads();

        float acc[4][8][4];
        #pragma unroll
        for (int i = 0; i < 4; i++)
            #pragma unroll
            for (int j = 0; j < 8; j++)
                #pragma unroll
                for (int r = 0; r < 4; r++) acc[i][j][r] = 0.0f;

        load_tile(0, 0);
        asm volatile("cp.async.wait_group 0;\n");
        __syncthreads();

        for (int kt = 0; kt < KT; kt++) {
            const int buf = kt & 1;
            const uint32_t aB = sA + buf * A_STG_B;
            const uint32_t bB = sB + buf * B_STG_B;

            if (kt + 1 < KT) load_tile(kt + 1, buf ^ 1);

            #pragma unroll
            for (int ks = 0; ks < 4; ks++) {
                const int kb = ks * 16;
                uint32_t af[4][4];
                #pragma unroll
                for (int tm = 0; tm < 4; tm++) {
                    uint32_t addr = aB +
                        ((warpM * 64 + tm * 16 + a_r) * HSTR + kb + a_c) * 2;
                    ldsm_x4(af[tm][0], af[tm][1], af[tm][2], af[tm][3], addr);
                }
                uint32_t bf[8][2];
                #pragma unroll
                for (int p = 0; p < 4; p++) {
                    uint32_t addr = bB +
                        ((kb + b_tr) * BSTR + warpN * 64 + p * 16 + b_tc) * 2;
                    ldsm_x4_t(bf[2*p][0], bf[2*p][1], bf[2*p+1][0], bf[2*p+1][1], addr);
                }
                #pragma unroll
                for (int tm = 0; tm < 4; tm++)
                    #pragma unroll
                    for (int tn = 0; tn < 8; tn++)
                        mma_f16(acc[tm][tn], af[tm], bf[tn][0], bf[tn][1]);
            }

            if (kt + 1 < KT) {
                asm volatile("cp.async.wait_group 0;\n");
                __syncthreads();
            }
        }

        // ---------------- epilogue ----------------
        __half* qkv_out = (MODE == 0)
            ? (which == 0 ? g_q : (which == 1 ? g_k : g_v)) : nullptr;
        const float qscale = (MODE == 0 && which == 0) ? 0.125f : 1.0f;

        #pragma unroll
        for (int tm = 0; tm < 4; tm++) {
            #pragma unroll
            for (int tn = 0; tn < 8; tn++) {
                const int n = n0 + warpN * 64 + tn * 8 + tkid * 2;
                const float bn0 = bias[n], bn1 = bias[n + 1];
                #pragma unroll
                for (int half_m = 0; half_m < 2; half_m++) {
                    const int m = m0 + warpM * 64 + tm * 16 + quad + half_m * 8;
                    float v0 = acc[tm][tn][half_m * 2    ] + bn0;
                    float v1 = acc[tm][tn][half_m * 2 + 1] + bn1;
                    if (MODE == 0) {
                        int b = m >> 10, s = m & 1023;
                        int h = n >> 6, hd = n & 63;
                        uint32_t pk = pack_h2(v0 * qscale, v1 * qscale);
                        *(uint32_t*)&qkv_out[(((size_t)b * Hh + h) * Ss + s) * HDd + hd] = pk;
                    } else if (MODE == 1) {
                        uint32_t pk = pack_h2(gelu_exact(v0), gelu_exact(v1));
                        *(uint32_t*)&g_h1[(size_t)m * N + n] = pk;
                    } else {
                        const float* rp = g_y + (size_t)m * N + n;
                        float2 o = make_float2(gelu_exact(v0) + rp[0],
                                               gelu_exact(v1) + rp[1]);
                        *(float2*)&Cout[(size_t)m * N + n] = o;
                    }
                }
            }
        }
    }
}

// =====================================================================
// FP16 flash attention v4 (validated, unchanged):
// block = 128 q rows, 4 warps x 32 rows, KV tile 64 rows, 2-buffer ring.
// =====================================================================
#define KSTRH 72
#define KVTILEH (64*KSTRH)
#define KVTILEB (KVTILEH*2)
#define ASMEM (4 * KVTILEB)

__global__ __launch_bounds__(128) void attn_tc(void)
{
    extern __shared__ __half asmem[];
    const int bh   = blockIdx.y;
    const int tid  = threadIdx.x;
    const int warp = tid >> 5;
    const int lane = tid & 31;
    const int quad = lane >> 2;
    const int tkid = lane & 3;

    const int q0 = blockIdx.x * 128 + warp * 32;
    const __half* kbase = g_k + (size_t)bh * Ss * HDd;
    const __half* vbase = g_v + (size_t)bh * Ss * HDd;

    uint32_t qf[2][4][4];
    #pragma unroll
    for (int mi = 0; mi < 2; mi++) {
        const __half* qb = g_q + ((size_t)bh * Ss + q0 + mi * 16) * HDd;
        #pragma unroll
        for (int kb = 0; kb < 4; kb++) {
            int c = kb * 16 + tkid * 2;
            qf[mi][kb][0] = *(const uint32_t*)&qb[(quad    ) * HDd + c    ];
            qf[mi][kb][1] = *(const uint32_t*)&qb[(quad + 8) * HDd + c    ];
            qf[mi][kb][2] = *(const uint32_t*)&qb[(quad    ) * HDd + c + 8];
            qf[mi][kb][3] = *(const uint32_t*)&qb[(quad + 8) * HDd + c + 8];
        }
    }

    float o[2][8][4];
    #pragma unroll
    for (int mi = 0; mi < 2; mi++)
        #pragma unroll
        for (int j = 0; j < 8; j++)
            #pragma unroll
            for (int r = 0; r < 4; r++) o[mi][j][r] = 0.0f;
    float mrow[2][2] = {{-1e30f, -1e30f}, {-1e30f, -1e30f}};
    float lrow[2][2] = {{0.0f, 0.0f}, {0.0f, 0.0f}};

    uint32_t sK = smem_u32(asmem);
    uint32_t sV = sK + 2 * KVTILEB;

    auto load_tile = [&](int t, int buf) {
        const __half* kp = kbase + (size_t)t * 64 * HDd;
        const __half* vp = vbase + (size_t)t * 64 * HDd;
        #pragma unroll
        for (int i = 0; i < 4; i++) {
            int idx = tid + i * 128;
            int row = idx >> 3;
            int c8  = (idx & 7) * 8;
            cp_async16(sK + buf * KVTILEB + (row * KSTRH + c8) * 2,
                       kp + row * HDd + c8);
            cp_async16(sV + buf * KVTILEB + (row * KSTRH + c8) * 2,
                       vp + row * HDd + c8);
        }
        asm volatile("cp.async.commit_group;\n");
    };

    const int NT = Ss / 64;
    load_tile(0, 0);
    asm volatile("cp.async.wait_group 0;\n");
    __syncthreads();

    const int kb_r = ((lane >> 4) * 8) + (lane & 7);
    const int kb_c = ((lane >> 3) & 1) * 8;
    const int vb_r = (((lane >> 3) & 1) * 8) + (lane & 7);
    const int vb_c = (lane >> 4) * 8;

    for (int t = 0; t < NT; t++) {
        const int buf = t & 1;
        const uint32_t kB = sK + buf * KVTILEB;
        const uint32_t vB = sV + buf * KVTILEB;

        if (t + 1 < NT) load_tile(t + 1, buf ^ 1);

        float sc[2][8][4];
        #pragma unroll
        for (int mi = 0; mi < 2; mi++)
            #pragma unroll
            for (int j = 0; j < 8; j++)
                #pragma unroll
                for (int r = 0; r < 4; r++) sc[mi][j][r] = 0.0f;

        #pragma unroll
        for (int kb = 0; kb < 4; kb++) {
            uint32_t bf[8][2];
            #pragma unroll
            for (int p = 0; p < 4; p++) {
                uint32_t addr = kB + ((p * 16 + kb_r) * KSTRH + kb * 16 + kb_c) * 2;
                ldsm_x4(bf[2*p][0], bf[2*p][1], bf[2*p+1][0], bf[2*p+1][1], addr);
            }
            #pragma unroll
            for (int j = 0; j < 8; j++) {
                mma_f16(sc[0][j], qf[0][kb], bf[j][0], bf[j][1]);
                mma_f16(sc[1][j], qf[1][kb], bf[j][0], bf[j][1]);
            }
        }

        #pragma unroll
        for (int mi = 0; mi < 2; mi++) {
            #pragma unroll
            for (int r = 0; r < 2; r++) {
                float tmax = -1e30f;
                #pragma unroll
                for (int j = 0; j < 8; j++)
                    tmax = fmaxf(tmax, fmaxf(sc[mi][j][2 * r], sc[mi][j][2 * r + 1]));
                tmax = fmaxf(tmax, __shfl_xor_sync(0xffffffffu, tmax, 1));
                tmax = fmaxf(tmax, __shfl_xor_sync(0xffffffffu, tmax, 2));

                float mnew = fmaxf(mrow[mi][r], tmax);
                float corr = __expf(mrow[mi][r] - mnew);
                mrow[mi][r] = mnew;
                lrow[mi][r] *= corr;
                #pragma unroll
                for (int j = 0; j < 8; j++) {
                    o[mi][j][2 * r]     *= corr;
                    o[mi][j][2 * r + 1] *= corr;
                }
            }
            #pragma unroll
            for (int j = 0; j < 8; j++) {
                sc[mi][j][0] = __expf(sc[mi][j][0] - mrow[mi][0]);
                sc[mi][j][1] = __expf(sc[mi][j][1] - mrow[mi][0]);
                sc[mi][j][2] = __expf(sc[mi][j][2] - mrow[mi][1]);
                sc[mi][j][3] = __expf(sc[mi][j][3] - mrow[mi][1]);
                lrow[mi][0] += sc[mi][j][0] + sc[mi][j][1];
                lrow[mi][1] += sc[mi][j][2] + sc[mi][j][3];
            }
        }

        #pragma unroll
        for (int th = 0; th < 4; th++) {
            uint32_t af[2][4];
            #pragma unroll
            for (int mi = 0; mi < 2; mi++) {
                af[mi][0] = pack_h2(sc[mi][2*th  ][0], sc[mi][2*th  ][1]);
                af[mi][1] = pack_h2(sc[mi][2*th  ][2], sc[mi][2*th  ][3]);
                af[mi][2] = pack_h2(sc[mi][2*th+1][0], sc[mi][2*th+1][1]);
                af[mi][3] = pack_h2(sc[mi][2*th+1][2], sc[mi][2*th+1][3]);
            }
            #pragma unroll
            for (int p = 0; p < 4; p++) {
                uint32_t vb[2][2];
                uint32_t addr = vB + ((th * 16 + vb_r) * KSTRH + p * 16 + vb_c) * 2;
                ldsm_x4_t(vb[0][0], vb[0][1], vb[1][0], vb[1][1], addr);
                #pragma unroll
                for (int mi = 0; mi < 2; mi++) {
                    mma_f16(o[mi][2*p  ], af[mi], vb[0][0], vb[0][1]);
                    mma_f16(o[mi][2*p+1], af[mi], vb[1][0], vb[1][1]);
                }
            }
        }

        if (t + 1 < NT) {
            asm volatile("cp.async.wait_group 0;\n");
            __syncthreads();
        }
    }

    #pragma unroll
    for (int mi = 0; mi < 2; mi++) {
        #pragma unroll
        for (int r = 0; r < 2; r++) {
            lrow[mi][r] += __shfl_xor_sync(0xffffffffu, lrow[mi][r], 1);
            lrow[mi][r] += __shfl_xor_sync(0xffffffffu, lrow[mi][r], 2);
        }
        float inv0 = 1.0f / lrow[mi][0];
        float inv1 = 1.0f / lrow[mi][1];

        float* ob0 = g_ctx + ((size_t)bh * Ss + q0 + mi * 16 + quad    ) * HDd;
        float* ob1 = g_ctx + ((size_t)bh * Ss + q0 + mi * 16 + quad + 8) * HDd;
        #pragma unroll
        for (int j = 0; j < 8; j++) {
            int col = j * 8 + tkid * 2;
            *(float2*)&ob0[col] = make_float2(o[mi][j][0] * inv0, o[mi][j][1] * inv0);
            *(float2*)&ob1[col] = make_float2(o[mi][j][2] * inv1, o[mi][j][3] * inv1);
        }
    }
}

// ---------------- fused LN1+LN2 ---------------------------------------------
__global__ __launch_bounds__(256) void ln_fused(
    const float* __restrict__ x,
    const float* __restrict__ g1, const float* __restrict__ b1,
    const float* __restrict__ g2, const float* __restrict__ b2)
{
    const int row = blockIdx.x;
    const int b = row >> 10, s = row & 1023;
    const int tid = threadIdx.x;

    __shared__ float rs[256], rq[256];

    float cv[3];
    float sum = 0.0f, sq = 0.0f;
    #pragma unroll
    for (int i = 0; i < 3; i++) {
        int col = tid + i * 256;
        int h = col >> 6, hd = col & 63;
        float c = g_ctx[(((size_t)b * Hh + h) * Ss + s) * HDd + hd];
        cv[i] = c;
        sum += c; sq += c * c;
    }
    rs[tid] = sum; rq[tid] = sq;
    __syncthreads();
    for (int o = 128; o > 0; o >>= 1) {
        if (tid < o) { rs[tid] += rs[tid + o]; rq[tid] += rq[tid + o]; }
        __syncthreads();
    }
    float mu = rs[0] * (1.0f / Dd);
    float var = rq[0] * (1.0f / Dd) - mu * mu;
    float rstd = rsqrtf(var + 1e-5f);

    float yv[3];
    float sum2 = 0.0f, sq2 = 0.0f;
    #pragma unroll
    for (int i = 0; i < 3; i++) {
        int col = tid + i * 256;
        float y = x[(size_t)row * Dd + col] +
                  (cv[i] - mu) * rstd * g1[col] + b1[col];
        yv[i] = y;
        sum2 += y; sq2 += y * y;
        g_y[(size_t)row * Dd + col] = y;
    }
    __syncthreads();
    rs[tid] = sum2; rq[tid] = sq2;
    __syncthreads();
    for (int o = 128; o > 0; o >>= 1) {
        if (tid < o) { rs[tid] += rs[tid + o]; rq[tid] += rq[tid + o]; }
        __syncthreads();
    }
    float mu2 = rs[0] * (1.0f / Dd);
    float var2 = rq[0] * (1.0f / Dd) - mu2 * mu2;
    float rstd2 = rsqrtf(var2 + 1e-5f);

    #pragma unroll
    for (int i = 0; i < 3; i++) {
        int col = tid + i * 256;
        g_ln2[(size_t)row * Dd + col] =
            __float2half_rn((yv[i] - mu2) * rstd2 * g2[col] + b2[col]);
    }
}

// ---------------- launch ----------------------------------------------------
extern "C" void kernel_launch(void* const* d_in, const int* in_sizes, int n_in,
                              void* d_out, int out_size)
{
    (void)in_sizes; (void)n_in; (void)out_size;
    const float* x     = (const float*)d_in[0];
    const float* wq    = (const float*)d_in[1];
    const float* bq    = (const float*)d_in[2];
    const float* wk    = (const float*)d_in[3];
    const float* bk    = (const float*)d_in[4];
    const float* wv    = (const float*)d_in[5];
    const float* bv    = (const float*)d_in[6];
    const float* ln1_g = (const float*)d_in[7];
    const float* ln1_b = (const float*)d_in[8];
    const float* ln2_g = (const float*)d_in[9];
    const float* ln2_b = (const float*)d_in[10];
    const float* w_in  = (const float*)d_in[11];
    const float* b_in  = (const float*)d_in[12];
    const float* w_out = (const float*)d_in[13];
    const float* b_out = (const float*)d_in[14];
    float* out = (float*)d_out;

    static int configured = 0;
    if (!configured) {
        cudaFuncSetAttribute(gemm_fp16<0>, cudaFuncAttributeMaxDynamicSharedMemorySize, GSMEM);
        cudaFuncSetAttribute(gemm_fp16<1>, cudaFuncAttributeMaxDynamicSharedMemorySize, GSMEM);
        cudaFuncSetAttribute(gemm_fp16<2>, cudaFuncAttributeMaxDynamicSharedMemorySize, GSMEM);
        cudaFuncSetAttribute(attn_tc, cudaFuncAttributeMaxDynamicSharedMemorySize, ASMEM);
        configured = 1;
    }

    // prep: fp32 -> fp16 at rest (no transpose; GEMM consumes [K,N] directly)
    prep_x<<<(Mm*Dd/4 + 255)/256, 256>>>(x, Mm*Dd/4);
    prep_w5<<<dim3((Dd*HIDh/4 + 255)/256, 1, 5), 256>>>(wq, wk, wv, w_in, w_out);

    // QKV projections (persistent tiles; 1152 logical tiles)
    {
        int nt = (Dd/128) * (Mm/128) * 3;
        int grid = nt < NPERS ? nt : NPERS;
        gemm_fp16<0><<<grid, 128, GSMEM>>>(bq, bk, bv, nullptr, Dd, Dd);
    }

    // attention -> g_ctx f32
    dim3 ga(Ss / 128, Bb * Hh);
    attn_tc<<<ga, 128, ASMEM>>>();

    // fused LN1 + LN2
    ln_fused<<<Mm, 256>>>(x, ln1_g, ln1_b, ln2_g, ln2_b);

    // MLP1 (1536 logical tiles)
    {
        int nt = (HIDh/128) * (Mm/128);
        int grid = nt < NPERS ? nt : NPERS;
        gemm_fp16<1><<<grid, 128, GSMEM>>>(b_in, nullptr, nullptr, nullptr, HIDh, Dd);
    }

    // MLP2 (384 tiles -> single wave)
    {
        int nt = (Dd/128) * (Mm/128);
        int grid = nt < NPERS ? nt : NPERS;
        gemm_fp16<2><<<grid, 128, GSMEM>>>(b_out, nullptr, nullptr, out, Dd, HIDh);
    }
}

// round 15
// speedup vs baseline: 1.1144x; 1.1144x over previous
#include <cuda_runtime.h>
#include <cuda_fp16.h>
#include <math.h>
#include <stdint.h>

#define Bb   8
#define Ss   1024
#define Dd   768
#define Hh   12
#define HDd  64
#define HIDh 3072
#define Mm   (Bb*Ss)   // 8192

// ---------------- scratch (device globals; no allocs allowed) ----------------
__device__ __half g_q   [(size_t)Mm*Dd];
__device__ __half g_k   [(size_t)Mm*Dd];
__device__ __half g_v   [(size_t)Mm*Dd];
__device__ __half g_ln2 [(size_t)Mm*Dd];
__device__ __half g_h1  [(size_t)Mm*HIDh];
__device__ __half g_xc  [(size_t)Mm*Dd];
__device__ __half g_wq  [(size_t)Dd*Dd];      // [K,N] original layout, fp16
__device__ __half g_wk  [(size_t)Dd*Dd];
__device__ __half g_wv  [(size_t)Dd*Dd];
__device__ __half g_win [(size_t)Dd*HIDh];
__device__ __half g_wout[(size_t)HIDh*Dd];
__device__ float g_ctx[(size_t)Mm*Dd];
__device__ float g_y  [(size_t)Mm*Dd];

__device__ __forceinline__ float gelu_exact(float x) {
    return 0.5f * x * (1.0f + erff(x * 0.70710678118654752f));
}
__device__ __forceinline__ void cp_async16(uint32_t saddr, const void* gaddr) {
    asm volatile("cp.async.cg.shared.global [%0], [%1], 16;\n" :: "r"(saddr), "l"(gaddr));
}
__device__ __forceinline__ uint32_t smem_u32(const void* p) {
    uint32_t a;
    asm("{ .reg .u64 t; cvta.to.shared.u64 t, %1; cvt.u32.u64 %0, t; }"
        : "=r"(a) : "l"(p));
    return a;
}
__device__ __forceinline__ void ldsm_x4(uint32_t& r0, uint32_t& r1,
                                        uint32_t& r2, uint32_t& r3, uint32_t a) {
    asm volatile("ldmatrix.sync.aligned.m8n8.x4.shared.b16 {%0,%1,%2,%3}, [%4];"
                 : "=r"(r0), "=r"(r1), "=r"(r2), "=r"(r3) : "r"(a));
}
__device__ __forceinline__ void ldsm_x4_t(uint32_t& r0, uint32_t& r1,
                                          uint32_t& r2, uint32_t& r3, uint32_t a) {
    asm volatile("ldmatrix.sync.aligned.m8n8.x4.trans.shared.b16 {%0,%1,%2,%3}, [%4];"
                 : "=r"(r0), "=r"(r1), "=r"(r2), "=r"(r3) : "r"(a));
}
__device__ __forceinline__ void mma_f16(float* c, const uint32_t* a,
                                        uint32_t b0, uint32_t b1) {
    asm volatile(
        "mma.sync.aligned.m16n8k16.row.col.f32.f16.f16.f32 "
        "{%0,%1,%2,%3},{%4,%5,%6,%7},{%8,%9},{%0,%1,%2,%3};"
        : "+f"(c[0]), "+f"(c[1]), "+f"(c[2]), "+f"(c[3])
        : "r"(a[0]), "r"(a[1]), "r"(a[2]), "r"(a[3]), "r"(b0), "r"(b1));
}
__device__ __forceinline__ uint32_t pack_h2(float a, float b) {
    __half2 h = __floats2half2_rn(a, b);
    return *(uint32_t*)&h;
}

// ---------------- prep kernels ----------------------------------------------
__global__ __launch_bounds__(256) void prep_x(const float* __restrict__ src, int n4)
{
    int i = blockIdx.x * 256 + threadIdx.x;
    if (i < n4) {
        float4 f = ((const float4*)src)[i];
        uint2 u;
        u.x = pack_h2(f.x, f.y);
        u.y = pack_h2(f.z, f.w);
        ((uint2*)g_xc)[i] = u;
    }
}

// one launch, z = 0..4 : wq wk wv win wout
__global__ __launch_bounds__(256) void prep_w5(const float* __restrict__ s0,
                                               const float* __restrict__ s1,
                                               const float* __restrict__ s2,
                                               const float* __restrict__ s3,
                                               const float* __restrict__ s4)
{
    const int id = blockIdx.z;
    const float* src = id == 0 ? s0 : id == 1 ? s1 : id == 2 ? s2
                     : id == 3 ? s3 : s4;
    __half* dst = id == 0 ? g_wq : id == 1 ? g_wk : id == 2 ? g_wv
                : id == 3 ? g_win : g_wout;
    const int n4 = (id < 3) ? (Dd*Dd/4) : (Dd*HIDh/4);
    int i = blockIdx.x * 256 + threadIdx.x;
    if (i < n4) {
        float4 f = ((const float4*)src)[i];
        uint2 u;
        u.x = pack_h2(f.x, f.y);
        u.y = pack_h2(f.z, f.w);
        ((uint2*)dst)[i] = u;
    }
}

// =====================================================================
// FP16 GEMM v7 (round-13 validated, non-persistent): CTA 128x128,
// 4 warps (2x2), warp tile 64x64, BK=64, 2-stage double buffer,
// ONE barrier per k-tile. A [M,K] ldsm; B [K,N] ldsm.trans.
// =====================================================================
#define HSTR 72
#define BSTR 136
#define A_STG_B (128*HSTR*2)        // 18432
#define B_STG_B (64*BSTR*2)         // 17408
#define GSMEM (2*A_STG_B + 2*B_STG_B)  // 71680

template<int MODE>
__global__ __launch_bounds__(128) void gemm_fp16(
    const float* __restrict__ bias0, const float* __restrict__ bias1,
    const float* __restrict__ bias2, float* __restrict__ Cout,
    int N, int K)
{
    extern __shared__ __half smem[];
    const int which = (MODE == 0) ? blockIdx.z : 0;

    const __half* A = (MODE == 0) ? g_xc : (MODE == 1 ? g_ln2 : g_h1);
    const __half* Bw = (MODE == 0)
        ? (which == 0 ? g_wq : (which == 1 ? g_wk : g_wv))
        : (MODE == 1 ? g_win : g_wout);
    const float* bias = (MODE == 0)
        ? (which == 0 ? bias0 : (which == 1 ? bias1 : bias2)) : bias0;

    const int tid  = threadIdx.x;
    const int lane = tid & 31;
    const int warp = tid >> 5;
    const int warpM = warp & 1;
    const int warpN = warp >> 1;
    const int quad = lane >> 2;
    const int tkid = lane & 3;

    const int m0 = blockIdx.y * 128;
    const int n0 = blockIdx.x * 128;

    uint32_t sA = smem_u32(smem);
    uint32_t sB = sA + 2 * A_STG_B;

    auto load_tile = [&](int kt, int buf) {
        const int k0 = kt * 64;
        #pragma unroll
        for (int i = 0; i < 8; i++) {
            int idx = tid + i * 128;
            int row = idx >> 3;
            int c8  = (idx & 7) * 8;
            cp_async16(sA + buf * A_STG_B + (row * HSTR + c8) * 2,
                       A + (size_t)(m0 + row) * K + k0 + c8);
        }
        #pragma unroll
        for (int i = 0; i < 8; i++) {
            int idx = tid + i * 128;
            int row = idx >> 4;
            int c8  = (idx & 15) * 8;
            cp_async16(sB + buf * B_STG_B + (row * BSTR + c8) * 2,
                       Bw + (size_t)(k0 + row) * N + n0 + c8);
        }
        asm volatile("cp.async.commit_group;\n");
    };

    float acc[4][8][4];
    #pragma unroll
    for (int i = 0; i < 4; i++)
        #pragma unroll
        for (int j = 0; j < 8; j++)
            #pragma unroll
            for (int r = 0; r < 4; r++) acc[i][j][r] = 0.0f;

    const int KT = K / 64;

    load_tile(0, 0);
    asm volatile("cp.async.wait_group 0;\n");
    __syncthreads();

    const int a_r = lane & 15;
    const int a_c = (lane >> 4) * 8;
    const int b_tr = (((lane >> 3) & 1) * 8) + (lane & 7);
    const int b_tc = (lane >> 4) * 8;

    for (int kt = 0; kt < KT; kt++) {
        const int buf = kt & 1;
        const uint32_t aB = sA + buf * A_STG_B;
        const uint32_t bB = sB + buf * B_STG_B;

        if (kt + 1 < KT) load_tile(kt + 1, buf ^ 1);

        #pragma unroll
        for (int ks = 0; ks < 4; ks++) {
            const int kb = ks * 16;
            uint32_t af[4][4];
            #pragma unroll
            for (int tm = 0; tm < 4; tm++) {
                uint32_t addr = aB +
                    ((warpM * 64 + tm * 16 + a_r) * HSTR + kb + a_c) * 2;
                ldsm_x4(af[tm][0], af[tm][1], af[tm][2], af[tm][3], addr);
            }
            uint32_t bf[8][2];
            #pragma unroll
            for (int p = 0; p < 4; p++) {
                uint32_t addr = bB +
                    ((kb + b_tr) * BSTR + warpN * 64 + p * 16 + b_tc) * 2;
                ldsm_x4_t(bf[2*p][0], bf[2*p][1], bf[2*p+1][0], bf[2*p+1][1], addr);
            }
            #pragma unroll
            for (int tm = 0; tm < 4; tm++)
                #pragma unroll
                for (int tn = 0; tn < 8; tn++)
                    mma_f16(acc[tm][tn], af[tm], bf[tn][0], bf[tn][1]);
        }

        if (kt + 1 < KT) {
            asm volatile("cp.async.wait_group 0;\n");
            __syncthreads();
        }
    }

    // ---------------- epilogue ----------------
    __half* qkv_out = (MODE == 0)
        ? (which == 0 ? g_q : (which == 1 ? g_k : g_v)) : nullptr;
    const float qscale = (MODE == 0 && which == 0) ? 0.125f : 1.0f;

    #pragma unroll
    for (int tm = 0; tm < 4; tm++) {
        #pragma unroll
        for (int tn = 0; tn < 8; tn++) {
            const int n = n0 + warpN * 64 + tn * 8 + tkid * 2;
            const float bn0 = bias[n], bn1 = bias[n + 1];
            #pragma unroll
            for (int half_m = 0; half_m < 2; half_m++) {
                const int m = m0 + warpM * 64 + tm * 16 + quad + half_m * 8;
                float v0 = acc[tm][tn][half_m * 2    ] + bn0;
                float v1 = acc[tm][tn][half_m * 2 + 1] + bn1;
                if (MODE == 0) {
                    int b = m >> 10, s = m & 1023;
                    int h = n >> 6, hd = n & 63;
                    uint32_t pk = pack_h2(v0 * qscale, v1 * qscale);
                    *(uint32_t*)&qkv_out[(((size_t)b * Hh + h) * Ss + s) * HDd + hd] = pk;
                } else if (MODE == 1) {
                    uint32_t pk = pack_h2(gelu_exact(v0), gelu_exact(v1));
                    *(uint32_t*)&g_h1[(size_t)m * N + n] = pk;
                } else {
                    const float* rp = g_y + (size_t)m * N + n;
                    float2 o = make_float2(gelu_exact(v0) + rp[0],
                                           gelu_exact(v1) + rp[1]);
                    *(float2*)&Cout[(size_t)m * N + n] = o;
                }
            }
        }
    }
}

// =====================================================================
// FP16 flash attention v4 (round-12 validated, unchanged):
// block = 128 q rows, 4 warps x 32 rows, KV tile 64 rows, 2-buffer ring.
// =====================================================================
#define KSTRH 72
#define KVTILEH (64*KSTRH)
#define KVTILEB (KVTILEH*2)
#define ASMEM (4 * KVTILEB)

__global__ __launch_bounds__(128) void attn_tc(void)
{
    extern __shared__ __half asmem[];
    const int bh   = blockIdx.y;
    const int tid  = threadIdx.x;
    const int warp = tid >> 5;
    const int lane = tid & 31;
    const int quad = lane >> 2;
    const int tkid = lane & 3;

    const int q0 = blockIdx.x * 128 + warp * 32;
    const __half* kbase = g_k + (size_t)bh * Ss * HDd;
    const __half* vbase = g_v + (size_t)bh * Ss * HDd;

    uint32_t qf[2][4][4];
    #pragma unroll
    for (int mi = 0; mi < 2; mi++) {
        const __half* qb = g_q + ((size_t)bh * Ss + q0 + mi * 16) * HDd;
        #pragma unroll
        for (int kb = 0; kb < 4; kb++) {
            int c = kb * 16 + tkid * 2;
            qf[mi][kb][0] = *(const uint32_t*)&qb[(quad    ) * HDd + c    ];
            qf[mi][kb][1] = *(const uint32_t*)&qb[(quad + 8) * HDd + c    ];
            qf[mi][kb][2] = *(const uint32_t*)&qb[(quad    ) * HDd + c + 8];
            qf[mi][kb][3] = *(const uint32_t*)&qb[(quad + 8) * HDd + c + 8];
        }
    }

    float o[2][8][4];
    #pragma unroll
    for (int mi = 0; mi < 2; mi++)
        #pragma unroll
        for (int j = 0; j < 8; j++)
            #pragma unroll
            for (int r = 0; r < 4; r++) o[mi][j][r] = 0.0f;
    float mrow[2][2] = {{-1e30f, -1e30f}, {-1e30f, -1e30f}};
    float lrow[2][2] = {{0.0f, 0.0f}, {0.0f, 0.0f}};

    uint32_t sK = smem_u32(asmem);
    uint32_t sV = sK + 2 * KVTILEB;

    auto load_tile = [&](int t, int buf) {
        const __half* kp = kbase + (size_t)t * 64 * HDd;
        const __half* vp = vbase + (size_t)t * 64 * HDd;
        #pragma unroll
        for (int i = 0; i < 4; i++) {
            int idx = tid + i * 128;
            int row = idx >> 3;
            int c8  = (idx & 7) * 8;
            cp_async16(sK + buf * KVTILEB + (row * KSTRH + c8) * 2,
                       kp + row * HDd + c8);
            cp_async16(sV + buf * KVTILEB + (row * KSTRH + c8) * 2,
                       vp + row * HDd + c8);
        }
        asm volatile("cp.async.commit_group;\n");
    };

    const int NT = Ss / 64;
    load_tile(0, 0);
    asm volatile("cp.async.wait_group 0;\n");
    __syncthreads();

    const int kb_r = ((lane >> 4) * 8) + (lane & 7);
    const int kb_c = ((lane >> 3) & 1) * 8;
    const int vb_r = (((lane >> 3) & 1) * 8) + (lane & 7);
    const int vb_c = (lane >> 4) * 8;

    for (int t = 0; t < NT; t++) {
        const int buf = t & 1;
        const uint32_t kB = sK + buf * KVTILEB;
        const uint32_t vB = sV + buf * KVTILEB;

        if (t + 1 < NT) load_tile(t + 1, buf ^ 1);

        float sc[2][8][4];
        #pragma unroll
        for (int mi = 0; mi < 2; mi++)
            #pragma unroll
            for (int j = 0; j < 8; j++)
                #pragma unroll
                for (int r = 0; r < 4; r++) sc[mi][j][r] = 0.0f;

        #pragma unroll
        for (int kb = 0; kb < 4; kb++) {
            uint32_t bf[8][2];
            #pragma unroll
            for (int p = 0; p < 4; p++) {
                uint32_t addr = kB + ((p * 16 + kb_r) * KSTRH + kb * 16 + kb_c) * 2;
                ldsm_x4(bf[2*p][0], bf[2*p][1], bf[2*p+1][0], bf[2*p+1][1], addr);
            }
            #pragma unroll
            for (int j = 0; j < 8; j++) {
                mma_f16(sc[0][j], qf[0][kb], bf[j][0], bf[j][1]);
                mma_f16(sc[1][j], qf[1][kb], bf[j][0], bf[j][1]);
            }
        }

        #pragma unroll
        for (int mi = 0; mi < 2; mi++) {
            #pragma unroll
            for (int r = 0; r < 2; r++) {
                float tmax = -1e30f;
                #pragma unroll
                for (int j = 0; j < 8; j++)
                    tmax = fmaxf(tmax, fmaxf(sc[mi][j][2 * r], sc[mi][j][2 * r + 1]));
                tmax = fmaxf(tmax, __shfl_xor_sync(0xffffffffu, tmax, 1));
                tmax = fmaxf(tmax, __shfl_xor_sync(0xffffffffu, tmax, 2));

                float mnew = fmaxf(mrow[mi][r], tmax);
                float corr = __expf(mrow[mi][r] - mnew);
                mrow[mi][r] = mnew;
                lrow[mi][r] *= corr;
                #pragma unroll
                for (int j = 0; j < 8; j++) {
                    o[mi][j][2 * r]     *= corr;
                    o[mi][j][2 * r + 1] *= corr;
                }
            }
            #pragma unroll
            for (int j = 0; j < 8; j++) {
                sc[mi][j][0] = __expf(sc[mi][j][0] - mrow[mi][0]);
                sc[mi][j][1] = __expf(sc[mi][j][1] - mrow[mi][0]);
                sc[mi][j][2] = __expf(sc[mi][j][2] - mrow[mi][1]);
                sc[mi][j][3] = __expf(sc[mi][j][3] - mrow[mi][1]);
                lrow[mi][0] += sc[mi][j][0] + sc[mi][j][1];
                lrow[mi][1] += sc[mi][j][2] + sc[mi][j][3];
            }
        }

        #pragma unroll
        for (int th = 0; th < 4; th++) {
            uint32_t af[2][4];
            #pragma unroll
            for (int mi = 0; mi < 2; mi++) {
                af[mi][0] = pack_h2(sc[mi][2*th  ][0], sc[mi][2*th  ][1]);
                af[mi][1] = pack_h2(sc[mi][2*th  ][2], sc[mi][2*th  ][3]);
                af[mi][2] = pack_h2(sc[mi][2*th+1][0], sc[mi][2*th+1][1]);
                af[mi][3] = pack_h2(sc[mi][2*th+1][2], sc[mi][2*th+1][3]);
            }
            #pragma unroll
            for (int p = 0; p < 4; p++) {
                uint32_t vb[2][2];
                uint32_t addr = vB + ((th * 16 + vb_r) * KSTRH + p * 16 + vb_c) * 2;
                ldsm_x4_t(vb[0][0], vb[0][1], vb[1][0], vb[1][1], addr);
                #pragma unroll
                for (int mi = 0; mi < 2; mi++) {
                    mma_f16(o[mi][2*p  ], af[mi], vb[0][0], vb[0][1]);
                    mma_f16(o[mi][2*p+1], af[mi], vb[1][0], vb[1][1]);
                }
            }
        }

        if (t + 1 < NT) {
            asm volatile("cp.async.wait_group 0;\n");
            __syncthreads();
        }
    }

    #pragma unroll
    for (int mi = 0; mi < 2; mi++) {
        #pragma unroll
        for (int r = 0; r < 2; r++) {
            lrow[mi][r] += __shfl_xor_sync(0xffffffffu, lrow[mi][r], 1);
            lrow[mi][r] += __shfl_xor_sync(0xffffffffu, lrow[mi][r], 2);
        }
        float inv0 = 1.0f / lrow[mi][0];
        float inv1 = 1.0f / lrow[mi][1];

        float* ob0 = g_ctx + ((size_t)bh * Ss + q0 + mi * 16 + quad    ) * HDd;
        float* ob1 = g_ctx + ((size_t)bh * Ss + q0 + mi * 16 + quad + 8) * HDd;
        #pragma unroll
        for (int j = 0; j < 8; j++) {
            int col = j * 8 + tkid * 2;
            *(float2*)&ob0[col] = make_float2(o[mi][j][0] * inv0, o[mi][j][1] * inv0);
            *(float2*)&ob1[col] = make_float2(o[mi][j][2] * inv1, o[mi][j][3] * inv1);
        }
    }
}

// ---------------- fused LN1+LN2 ---------------------------------------------
__global__ __launch_bounds__(256) void ln_fused(
    const float* __restrict__ x,
    const float* __restrict__ g1, const float* __restrict__ b1,
    const float* __restrict__ g2, const float* __restrict__ b2)
{
    const int row = blockIdx.x;
    const int b = row >> 10, s = row & 1023;
    const int tid = threadIdx.x;

    __shared__ float rs[256], rq[256];

    float cv[3];
    float sum = 0.0f, sq = 0.0f;
    #pragma unroll
    for (int i = 0; i < 3; i++) {
        int col = tid + i * 256;
        int h = col >> 6, hd = col & 63;
        float c = g_ctx[(((size_t)b * Hh + h) * Ss + s) * HDd + hd];
        cv[i] = c;
        sum += c; sq += c * c;
    }
    rs[tid] = sum; rq[tid] = sq;
    __syncthreads();
    for (int o = 128; o > 0; o >>= 1) {
        if (tid < o) { rs[tid] += rs[tid + o]; rq[tid] += rq[tid + o]; }
        __syncthreads();
    }
    float mu = rs[0] * (1.0f / Dd);
    float var = rq[0] * (1.0f / Dd) - mu * mu;
    float rstd = rsqrtf(var + 1e-5f);

    float yv[3];
    float sum2 = 0.0f, sq2 = 0.0f;
    #pragma unroll
    for (int i = 0; i < 3; i++) {
        int col = tid + i * 256;
        float y = x[(size_t)row * Dd + col] +
                  (cv[i] - mu) * rstd * g1[col] + b1[col];
        yv[i] = y;
        sum2 += y; sq2 += y * y;
        g_y[(size_t)row * Dd + col] = y;
    }
    __syncthreads();
    rs[tid] = sum2; rq[tid] = sq2;
    __syncthreads();
    for (int o = 128; o > 0; o >>= 1) {
        if (tid < o) { rs[tid] += rs[tid + o]; rq[tid] += rq[tid + o]; }
        __syncthreads();
    }
    float mu2 = rs[0] * (1.0f / Dd);
    float var2 = rq[0] * (1.0f / Dd) - mu2 * mu2;
    float rstd2 = rsqrtf(var2 + 1e-5f);

    #pragma unroll
    for (int i = 0; i < 3; i++) {
        int col = tid + i * 256;
        g_ln2[(size_t)row * Dd + col] =
            __float2half_rn((yv[i] - mu2) * rstd2 * g2[col] + b2[col]);
    }
}

// ---------------- launch ----------------------------------------------------
extern "C" void kernel_launch(void* const* d_in, const int* in_sizes, int n_in,
                              void* d_out, int out_size)
{
    (void)in_sizes; (void)n_in; (void)out_size;
    const float* x     = (const float*)d_in[0];
    const float* wq    = (const float*)d_in[1];
    const float* bq    = (const float*)d_in[2];
    const float* wk    = (const float*)d_in[3];
    const float* bk    = (const float*)d_in[4];
    const float* wv    = (const float*)d_in[5];
    const float* bv    = (const float*)d_in[6];
    const float* ln1_g = (const float*)d_in[7];
    const float* ln1_b = (const float*)d_in[8];
    const float* ln2_g = (const float*)d_in[9];
    const float* ln2_b = (const float*)d_in[10];
    const float* w_in  = (const float*)d_in[11];
    const float* b_in  = (const float*)d_in[12];
    const float* w_out = (const float*)d_in[13];
    const float* b_out = (const float*)d_in[14];
    float* out = (float*)d_out;

    static int configured = 0;
    if (!configured) {
        cudaFuncSetAttribute(gemm_fp16<0>, cudaFuncAttributeMaxDynamicSharedMemorySize, GSMEM);
        cudaFuncSetAttribute(gemm_fp16<1>, cudaFuncAttributeMaxDynamicSharedMemorySize, GSMEM);
        cudaFuncSetAttribute(gemm_fp16<2>, cudaFuncAttributeMaxDynamicSharedMemorySize, GSMEM);
        cudaFuncSetAttribute(attn_tc, cudaFuncAttributeMaxDynamicSharedMemorySize, ASMEM);
        configured = 1;
    }

    // prep: fp32 -> fp16 at rest (no transpose; GEMM consumes [K,N] directly)
    prep_x<<<(Mm*Dd/4 + 255)/256, 256>>>(x, Mm*Dd/4);
    prep_w5<<<dim3((Dd*HIDh/4 + 255)/256, 1, 5), 256>>>(wq, wk, wv, w_in, w_out);

    // QKV projections (one launch, z = q/k/v)
    dim3 gq(Dd / 128, Mm / 128, 3);
    gemm_fp16<0><<<gq, 128, GSMEM>>>(bq, bk, bv, nullptr, Dd, Dd);

    // attention -> g_ctx f32
    dim3 ga(Ss / 128, Bb * Hh);
    attn_tc<<<ga, 128, ASMEM>>>();

    // fused LN1 + LN2
    ln_fused<<<Mm, 256>>>(x, ln1_g, ln1_b, ln2_g, ln2_b);

    // MLP
    dim3 g1(HIDh / 128, Mm / 128);
    gemm_fp16<1><<<g1, 128, GSMEM>>>(b_in, nullptr, nullptr, nullptr, HIDh, Dd);

    dim3 g2(Dd / 128, Mm / 128);
    gemm_fp16<2><<<g2, 128, GSMEM>>>(b_out, nullptr, nullptr, out, Dd, HIDh);
}

// round 16
// speedup vs baseline: 1.1167x; 1.0021x over previous
#include <cuda_runtime.h>
#include <cuda_fp16.h>
#include <math.h>
#include <stdint.h>

#define Bb   8
#define Ss   1024
#define Dd   768
#define Hh   12
#define HDd  64
#define HIDh 3072
#define Mm   (Bb*Ss)   // 8192

// ---------------- scratch (device globals; no allocs allowed) ----------------
__device__ __half g_q   [(size_t)Mm*Dd];
__device__ __half g_k   [(size_t)Mm*Dd];
__device__ __half g_v   [(size_t)Mm*Dd];
__device__ __half g_ln2 [(size_t)Mm*Dd];
__device__ __half g_h1  [(size_t)Mm*HIDh];
__device__ __half g_xc  [(size_t)Mm*Dd];
__device__ __half g_wq  [(size_t)Dd*Dd];      // [K,N] original layout, fp16
__device__ __half g_wk  [(size_t)Dd*Dd];
__device__ __half g_wv  [(size_t)Dd*Dd];
__device__ __half g_win [(size_t)Dd*HIDh];
__device__ __half g_wout[(size_t)HIDh*Dd];
__device__ __half g_ctxh[(size_t)Mm*Dd];      // fp16 attention output
__device__ float g_y  [(size_t)Mm*Dd];

__device__ __forceinline__ float gelu_exact(float x) {
    return 0.5f * x * (1.0f + erff(x * 0.70710678118654752f));
}
__device__ __forceinline__ void cp_async16(uint32_t saddr, const void* gaddr) {
    asm volatile("cp.async.cg.shared.global [%0], [%1], 16;\n" :: "r"(saddr), "l"(gaddr));
}
__device__ __forceinline__ uint32_t smem_u32(const void* p) {
    uint32_t a;
    asm("{ .reg .u64 t; cvta.to.shared.u64 t, %1; cvt.u32.u64 %0, t; }"
        : "=r"(a) : "l"(p));
    return a;
}
__device__ __forceinline__ void ldsm_x4(uint32_t& r0, uint32_t& r1,
                                        uint32_t& r2, uint32_t& r3, uint32_t a) {
    asm volatile("ldmatrix.sync.aligned.m8n8.x4.shared.b16 {%0,%1,%2,%3}, [%4];"
                 : "=r"(r0), "=r"(r1), "=r"(r2), "=r"(r3) : "r"(a));
}
__device__ __forceinline__ void ldsm_x4_t(uint32_t& r0, uint32_t& r1,
                                          uint32_t& r2, uint32_t& r3, uint32_t a) {
    asm volatile("ldmatrix.sync.aligned.m8n8.x4.trans.shared.b16 {%0,%1,%2,%3}, [%4];"
                 : "=r"(r0), "=r"(r1), "=r"(r2), "=r"(r3) : "r"(a));
}
__device__ __forceinline__ void mma_f16(float* c, const uint32_t* a,
                                        uint32_t b0, uint32_t b1) {
    asm volatile(
        "mma.sync.aligned.m16n8k16.row.col.f32.f16.f16.f32 "
        "{%0,%1,%2,%3},{%4,%5,%6,%7},{%8,%9},{%0,%1,%2,%3};"
        : "+f"(c[0]), "+f"(c[1]), "+f"(c[2]), "+f"(c[3])
        : "r"(a[0]), "r"(a[1]), "r"(a[2]), "r"(a[3]), "r"(b0), "r"(b1));
}
__device__ __forceinline__ uint32_t pack_h2(float a, float b) {
    __half2 h = __floats2half2_rn(a, b);
    return *(uint32_t*)&h;
}

// ---------------- prep kernels ----------------------------------------------
__global__ __launch_bounds__(256) void prep_x(const float* __restrict__ src, int n4)
{
    int i = blockIdx.x * 256 + threadIdx.x;
    if (i < n4) {
        float4 f = ((const float4*)src)[i];
        uint2 u;
        u.x = pack_h2(f.x, f.y);
        u.y = pack_h2(f.z, f.w);
        ((uint2*)g_xc)[i] = u;
    }
}

// one launch, z = 0..4 : wq wk wv win wout
__global__ __launch_bounds__(256) void prep_w5(const float* __restrict__ s0,
                                               const float* __restrict__ s1,
                                               const float* __restrict__ s2,
                                               const float* __restrict__ s3,
                                               const float* __restrict__ s4)
{
    const int id = blockIdx.z;
    const float* src = id == 0 ? s0 : id == 1 ? s1 : id == 2 ? s2
                     : id == 3 ? s3 : s4;
    __half* dst = id == 0 ? g_wq : id == 1 ? g_wk : id == 2 ? g_wv
                : id == 3 ? g_win : g_wout;
    const int n4 = (id < 3) ? (Dd*Dd/4) : (Dd*HIDh/4);
    int i = blockIdx.x * 256 + threadIdx.x;
    if (i < n4) {
        float4 f = ((const float4*)src)[i];
        uint2 u;
        u.x = pack_h2(f.x, f.y);
        u.y = pack_h2(f.z, f.w);
        ((uint2*)dst)[i] = u;
    }
}

// =====================================================================
// FP16 GEMM v7 (validated): CTA 128x128, 4 warps (2x2), warp 64x64,
// BK=64, 2-stage double buffer, ONE barrier per k-tile.
// A [M,K] ldsm; B [K,N] ldsm.trans.
// =====================================================================
#define HSTR 72
#define BSTR 136
#define A_STG_B (128*HSTR*2)        // 18432
#define B_STG_B (64*BSTR*2)         // 17408
#define GSMEM (2*A_STG_B + 2*B_STG_B)  // 71680

template<int MODE>
__global__ __launch_bounds__(128) void gemm_fp16(
    const float* __restrict__ bias0, const float* __restrict__ bias1,
    const float* __restrict__ bias2, float* __restrict__ Cout,
    int N, int K)
{
    extern __shared__ __half smem[];
    const int which = (MODE == 0) ? blockIdx.z : 0;

    const __half* A = (MODE == 0) ? g_xc : (MODE == 1 ? g_ln2 : g_h1);
    const __half* Bw = (MODE == 0)
        ? (which == 0 ? g_wq : (which == 1 ? g_wk : g_wv))
        : (MODE == 1 ? g_win : g_wout);
    const float* bias = (MODE == 0)
        ? (which == 0 ? bias0 : (which == 1 ? bias1 : bias2)) : bias0;

    const int tid  = threadIdx.x;
    const int lane = tid & 31;
    const int warp = tid >> 5;
    const int warpM = warp & 1;
    const int warpN = warp >> 1;
    const int quad = lane >> 2;
    const int tkid = lane & 3;

    const int m0 = blockIdx.y * 128;
    const int n0 = blockIdx.x * 128;

    uint32_t sA = smem_u32(smem);
    uint32_t sB = sA + 2 * A_STG_B;

    auto load_tile = [&](int kt, int buf) {
        const int k0 = kt * 64;
        #pragma unroll
        for (int i = 0; i < 8; i++) {
            int idx = tid + i * 128;
            int row = idx >> 3;
            int c8  = (idx & 7) * 8;
            cp_async16(sA + buf * A_STG_B + (row * HSTR + c8) * 2,
                       A + (size_t)(m0 + row) * K + k0 + c8);
        }
        #pragma unroll
        for (int i = 0; i < 8; i++) {
            int idx = tid + i * 128;
            int row = idx >> 4;
            int c8  = (idx & 15) * 8;
            cp_async16(sB + buf * B_STG_B + (row * BSTR + c8) * 2,
                       Bw + (size_t)(k0 + row) * N + n0 + c8);
        }
        asm volatile("cp.async.commit_group;\n");
    };

    float acc[4][8][4];
    #pragma unroll
    for (int i = 0; i < 4; i++)
        #pragma unroll
        for (int j = 0; j < 8; j++)
            #pragma unroll
            for (int r = 0; r < 4; r++) acc[i][j][r] = 0.0f;

    const int KT = K / 64;

    load_tile(0, 0);
    asm volatile("cp.async.wait_group 0;\n");
    __syncthreads();

    const int a_r = lane & 15;
    const int a_c = (lane >> 4) * 8;
    const int b_tr = (((lane >> 3) & 1) * 8) + (lane & 7);
    const int b_tc = (lane >> 4) * 8;

    for (int kt = 0; kt < KT; kt++) {
        const int buf = kt & 1;
        const uint32_t aB = sA + buf * A_STG_B;
        const uint32_t bB = sB + buf * B_STG_B;

        if (kt + 1 < KT) load_tile(kt + 1, buf ^ 1);

        #pragma unroll
        for (int ks = 0; ks < 4; ks++) {
            const int kb = ks * 16;
            uint32_t af[4][4];
            #pragma unroll
            for (int tm = 0; tm < 4; tm++) {
                uint32_t addr = aB +
                    ((warpM * 64 + tm * 16 + a_r) * HSTR + kb + a_c) * 2;
                ldsm_x4(af[tm][0], af[tm][1], af[tm][2], af[tm][3], addr);
            }
            uint32_t bf[8][2];
            #pragma unroll
            for (int p = 0; p < 4; p++) {
                uint32_t addr = bB +
                    ((kb + b_tr) * BSTR + warpN * 64 + p * 16 + b_tc) * 2;
                ldsm_x4_t(bf[2*p][0], bf[2*p][1], bf[2*p+1][0], bf[2*p+1][1], addr);
            }
            #pragma unroll
            for (int tm = 0; tm < 4; tm++)
                #pragma unroll
                for (int tn = 0; tn < 8; tn++)
                    mma_f16(acc[tm][tn], af[tm], bf[tn][0], bf[tn][1]);
        }

        if (kt + 1 < KT) {
            asm volatile("cp.async.wait_group 0;\n");
            __syncthreads();
        }
    }

    // ---------------- epilogue ----------------
    __half* qkv_out = (MODE == 0)
        ? (which == 0 ? g_q : (which == 1 ? g_k : g_v)) : nullptr;
    const float qscale = (MODE == 0 && which == 0) ? 0.125f : 1.0f;

    #pragma unroll
    for (int tm = 0; tm < 4; tm++) {
        #pragma unroll
        for (int tn = 0; tn < 8; tn++) {
            const int n = n0 + warpN * 64 + tn * 8 + tkid * 2;
            const float bn0 = bias[n], bn1 = bias[n + 1];
            #pragma unroll
            for (int half_m = 0; half_m < 2; half_m++) {
                const int m = m0 + warpM * 64 + tm * 16 + quad + half_m * 8;
                float v0 = acc[tm][tn][half_m * 2    ] + bn0;
                float v1 = acc[tm][tn][half_m * 2 + 1] + bn1;
                if (MODE == 0) {
                    int b = m >> 10, s = m & 1023;
                    int h = n >> 6, hd = n & 63;
                    uint32_t pk = pack_h2(v0 * qscale, v1 * qscale);
                    *(uint32_t*)&qkv_out[(((size_t)b * Hh + h) * Ss + s) * HDd + hd] = pk;
                } else if (MODE == 1) {
                    uint32_t pk = pack_h2(gelu_exact(v0), gelu_exact(v1));
                    *(uint32_t*)&g_h1[(size_t)m * N + n] = pk;
                } else {
                    const float* rp = g_y + (size_t)m * N + n;
                    float2 o = make_float2(gelu_exact(v0) + rp[0],
                                           gelu_exact(v1) + rp[1]);
                    *(float2*)&Cout[(size_t)m * N + n] = o;
                }
            }
        }
    }
}

// =====================================================================
// FP16 flash attention v4 (validated): block = 128 q rows, 4 warps x
// 32 rows, KV tile 64 rows, 2-buffer ring. Output now fp16 (g_ctxh).
// =====================================================================
#define KSTRH 72
#define KVTILEH (64*KSTRH)
#define KVTILEB (KVTILEH*2)
#define ASMEM (4 * KVTILEB)

__global__ __launch_bounds__(128) void attn_tc(void)
{
    extern __shared__ __half asmem[];
    const int bh   = blockIdx.y;
    const int tid  = threadIdx.x;
    const int warp = tid >> 5;
    const int lane = tid & 31;
    const int quad = lane >> 2;
    const int tkid = lane & 3;

    const int q0 = blockIdx.x * 128 + warp * 32;
    const __half* kbase = g_k + (size_t)bh * Ss * HDd;
    const __half* vbase = g_v + (size_t)bh * Ss * HDd;

    uint32_t qf[2][4][4];
    #pragma unroll
    for (int mi = 0; mi < 2; mi++) {
        const __half* qb = g_q + ((size_t)bh * Ss + q0 + mi * 16) * HDd;
        #pragma unroll
        for (int kb = 0; kb < 4; kb++) {
            int c = kb * 16 + tkid * 2;
            qf[mi][kb][0] = *(const uint32_t*)&qb[(quad    ) * HDd + c    ];
            qf[mi][kb][1] = *(const uint32_t*)&qb[(quad + 8) * HDd + c    ];
            qf[mi][kb][2] = *(const uint32_t*)&qb[(quad    ) * HDd + c + 8];
            qf[mi][kb][3] = *(const uint32_t*)&qb[(quad + 8) * HDd + c + 8];
        }
    }

    float o[2][8][4];
    #pragma unroll
    for (int mi = 0; mi < 2; mi++)
        #pragma unroll
        for (int j = 0; j < 8; j++)
            #pragma unroll
            for (int r = 0; r < 4; r++) o[mi][j][r] = 0.0f;
    float mrow[2][2] = {{-1e30f, -1e30f}, {-1e30f, -1e30f}};
    float lrow[2][2] = {{0.0f, 0.0f}, {0.0f, 0.0f}};

    uint32_t sK = smem_u32(asmem);
    uint32_t sV = sK + 2 * KVTILEB;

    auto load_tile = [&](int t, int buf) {
        const __half* kp = kbase + (size_t)t * 64 * HDd;
        const __half* vp = vbase + (size_t)t * 64 * HDd;
        #pragma unroll
        for (int i = 0; i < 4; i++) {
            int idx = tid + i * 128;
            int row = idx >> 3;
            int c8  = (idx & 7) * 8;
            cp_async16(sK + buf * KVTILEB + (row * KSTRH + c8) * 2,
                       kp + row * HDd + c8);
            cp_async16(sV + buf * KVTILEB + (row * KSTRH + c8) * 2,
                       vp + row * HDd + c8);
        }
        asm volatile("cp.async.commit_group;\n");
    };

    const int NT = Ss / 64;
    load_tile(0, 0);
    asm volatile("cp.async.wait_group 0;\n");
    __syncthreads();

    const int kb_r = ((lane >> 4) * 8) + (lane & 7);
    const int kb_c = ((lane >> 3) & 1) * 8;
    const int vb_r = (((lane >> 3) & 1) * 8) + (lane & 7);
    const int vb_c = (lane >> 4) * 8;

    for (int t = 0; t < NT; t++) {
        const int buf = t & 1;
        const uint32_t kB = sK + buf * KVTILEB;
        const uint32_t vB = sV + buf * KVTILEB;

        if (t + 1 < NT) load_tile(t + 1, buf ^ 1);

        float sc[2][8][4];
        #pragma unroll
        for (int mi = 0; mi < 2; mi++)
            #pragma unroll
            for (int j = 0; j < 8; j++)
                #pragma unroll
                for (int r = 0; r < 4; r++) sc[mi][j][r] = 0.0f;

        #pragma unroll
        for (int kb = 0; kb < 4; kb++) {
            uint32_t bf[8][2];
            #pragma unroll
            for (int p = 0; p < 4; p++) {
                uint32_t addr = kB + ((p * 16 + kb_r) * KSTRH + kb * 16 + kb_c) * 2;
                ldsm_x4(bf[2*p][0], bf[2*p][1], bf[2*p+1][0], bf[2*p+1][1], addr);
            }
            #pragma unroll
            for (int j = 0; j < 8; j++) {
                mma_f16(sc[0][j], qf[0][kb], bf[j][0], bf[j][1]);
                mma_f16(sc[1][j], qf[1][kb], bf[j][0], bf[j][1]);
            }
        }

        #pragma unroll
        for (int mi = 0; mi < 2; mi++) {
            #pragma unroll
            for (int r = 0; r < 2; r++) {
                float tmax = -1e30f;
                #pragma unroll
                for (int j = 0; j < 8; j++)
                    tmax = fmaxf(tmax, fmaxf(sc[mi][j][2 * r], sc[mi][j][2 * r + 1]));
                tmax = fmaxf(tmax, __shfl_xor_sync(0xffffffffu, tmax, 1));
                tmax = fmaxf(tmax, __shfl_xor_sync(0xffffffffu, tmax, 2));

                float mnew = fmaxf(mrow[mi][r], tmax);
                float corr = __expf(mrow[mi][r] - mnew);
                mrow[mi][r] = mnew;
                lrow[mi][r] *= corr;
                #pragma unroll
                for (int j = 0; j < 8; j++) {
                    o[mi][j][2 * r]     *= corr;
                    o[mi][j][2 * r + 1] *= corr;
                }
            }
            #pragma unroll
            for (int j = 0; j < 8; j++) {
                sc[mi][j][0] = __expf(sc[mi][j][0] - mrow[mi][0]);
                sc[mi][j][1] = __expf(sc[mi][j][1] - mrow[mi][0]);
                sc[mi][j][2] = __expf(sc[mi][j][2] - mrow[mi][1]);
                sc[mi][j][3] = __expf(sc[mi][j][3] - mrow[mi][1]);
                lrow[mi][0] += sc[mi][j][0] + sc[mi][j][1];
                lrow[mi][1] += sc[mi][j][2] + sc[mi][j][3];
            }
        }

        #pragma unroll
        for (int th = 0; th < 4; th++) {
            uint32_t af[2][4];
            #pragma unroll
            for (int mi = 0; mi < 2; mi++) {
                af[mi][0] = pack_h2(sc[mi][2*th  ][0], sc[mi][2*th  ][1]);
                af[mi][1] = pack_h2(sc[mi][2*th  ][2], sc[mi][2*th  ][3]);
                af[mi][2] = pack_h2(sc[mi][2*th+1][0], sc[mi][2*th+1][1]);
                af[mi][3] = pack_h2(sc[mi][2*th+1][2], sc[mi][2*th+1][3]);
            }
            #pragma unroll
            for (int p = 0; p < 4; p++) {
                uint32_t vb[2][2];
                uint32_t addr = vB + ((th * 16 + vb_r) * KSTRH + p * 16 + vb_c) * 2;
                ldsm_x4_t(vb[0][0], vb[0][1], vb[1][0], vb[1][1], addr);
                #pragma unroll
                for (int mi = 0; mi < 2; mi++) {
                    mma_f16(o[mi][2*p  ], af[mi], vb[0][0], vb[0][1]);
                    mma_f16(o[mi][2*p+1], af[mi], vb[1][0], vb[1][1]);
                }
            }
        }

        if (t + 1 < NT) {
            asm volatile("cp.async.wait_group 0;\n");
            __syncthreads();
        }
    }

    #pragma unroll
    for (int mi = 0; mi < 2; mi++) {
        #pragma unroll
        for (int r = 0; r < 2; r++) {
            lrow[mi][r] += __shfl_xor_sync(0xffffffffu, lrow[mi][r], 1);
            lrow[mi][r] += __shfl_xor_sync(0xffffffffu, lrow[mi][r], 2);
        }
        float inv0 = 1.0f / lrow[mi][0];
        float inv1 = 1.0f / lrow[mi][1];

        __half* ob0 = g_ctxh + ((size_t)bh * Ss + q0 + mi * 16 + quad    ) * HDd;
        __half* ob1 = g_ctxh + ((size_t)bh * Ss + q0 + mi * 16 + quad + 8) * HDd;
        #pragma unroll
        for (int j = 0; j < 8; j++) {
            int col = j * 8 + tkid * 2;
            *(uint32_t*)&ob0[col] = pack_h2(o[mi][j][0] * inv0, o[mi][j][1] * inv0);
            *(uint32_t*)&ob1[col] = pack_h2(o[mi][j][2] * inv1, o[mi][j][3] * inv1);
        }
    }
}

// ---------------- fused LN1+LN2 (ctx now fp16) -------------------------------
__global__ __launch_bounds__(256) void ln_fused(
    const float* __restrict__ x,
    const float* __restrict__ g1, const float* __restrict__ b1,
    const float* __restrict__ g2, const float* __restrict__ b2)
{
    const int row = blockIdx.x;
    const int b = row >> 10, s = row & 1023;
    const int tid = threadIdx.x;

    __shared__ float rs[256], rq[256];

    float cv[3];
    float sum = 0.0f, sq = 0.0f;
    #pragma unroll
    for (int i = 0; i < 3; i++) {
        int col = tid + i * 256;
        int h = col >> 6, hd = col & 63;
        float c = __half2float(g_ctxh[(((size_t)b * Hh + h) * Ss + s) * HDd + hd]);
        cv[i] = c;
        sum += c; sq += c * c;
    }
    rs[tid] = sum; rq[tid] = sq;
    __syncthreads();
    for (int o = 128; o > 0; o >>= 1) {
        if (tid < o) { rs[tid] += rs[tid + o]; rq[tid] += rq[tid + o]; }
        __syncthreads();
    }
    float mu = rs[0] * (1.0f / Dd);
    float var = rq[0] * (1.0f / Dd) - mu * mu;
    float rstd = rsqrtf(var + 1e-5f);

    float yv[3];
    float sum2 = 0.0f, sq2 = 0.0f;
    #pragma unroll
    for (int i = 0; i < 3; i++) {
        int col = tid + i * 256;
        float y = x[(size_t)row * Dd + col] +
                  (cv[i] - mu) * rstd * g1[col] + b1[col];
        yv[i] = y;
        sum2 += y; sq2 += y * y;
        g_y[(size_t)row * Dd + col] = y;
    }
    __syncthreads();
    rs[tid] = sum2; rq[tid] = sq2;
    __syncthreads();
    for (int o = 128; o > 0; o >>= 1) {
        if (tid < o) { rs[tid] += rs[tid + o]; rq[tid] += rq[tid + o]; }
        __syncthreads();
    }
    float mu2 = rs[0] * (1.0f / Dd);
    float var2 = rq[0] * (1.0f / Dd) - mu2 * mu2;
    float rstd2 = rsqrtf(var2 + 1e-5f);

    #pragma unroll
    for (int i = 0; i < 3; i++) {
        int col = tid + i * 256;
        g_ln2[(size_t)row * Dd + col] =
            __float2half_rn((yv[i] - mu2) * rstd2 * g2[col] + b2[col]);
    }
}

// ---------------- launch ----------------------------------------------------
extern "C" void kernel_launch(void* const* d_in, const int* in_sizes, int n_in,
                              void* d_out, int out_size)
{
    (void)in_sizes; (void)n_in; (void)out_size;
    const float* x     = (const float*)d_in[0];
    const float* wq    = (const float*)d_in[1];
    const float* bq    = (const float*)d_in[2];
    const float* wk    = (const float*)d_in[3];
    const float* bk    = (const float*)d_in[4];
    const float* wv    = (const float*)d_in[5];
    const float* bv    = (const float*)d_in[6];
    const float* ln1_g = (const float*)d_in[7];
    const float* ln1_b = (const float*)d_in[8];
    const float* ln2_g = (const float*)d_in[9];
    const float* ln2_b = (const float*)d_in[10];
    const float* w_in  = (const float*)d_in[11];
    const float* b_in  = (const float*)d_in[12];
    const float* w_out = (const float*)d_in[13];
    const float* b_out = (const float*)d_in[14];
    float* out = (float*)d_out;

    static int configured = 0;
    if (!configured) {
        cudaFuncSetAttribute(gemm_fp16<0>, cudaFuncAttributeMaxDynamicSharedMemorySize, GSMEM);
        cudaFuncSetAttribute(gemm_fp16<1>, cudaFuncAttributeMaxDynamicSharedMemorySize, GSMEM);
        cudaFuncSetAttribute(gemm_fp16<2>, cudaFuncAttributeMaxDynamicSharedMemorySize, GSMEM);
        cudaFuncSetAttribute(attn_tc, cudaFuncAttributeMaxDynamicSharedMemorySize, ASMEM);
        configured = 1;
    }

    // prep: fp32 -> fp16 at rest (no transpose; GEMM consumes [K,N] directly)
    prep_x<<<(Mm*Dd/4 + 255)/256, 256>>>(x, Mm*Dd/4);
    prep_w5<<<dim3((Dd*HIDh/4 + 255)/256, 1, 5), 256>>>(wq, wk, wv, w_in, w_out);

    // QKV projections (one launch, z = q/k/v)
    dim3 gq(Dd / 128, Mm / 128, 3);
    gemm_fp16<0><<<gq, 128, GSMEM>>>(bq, bk, bv, nullptr, Dd, Dd);

    // attention -> g_ctxh fp16
    dim3 ga(Ss / 128, Bb * Hh);
    attn_tc<<<ga, 128, ASMEM>>>();

    // fused LN1 + LN2
    ln_fused<<<Mm, 256>>>(x, ln1_g, ln1_b, ln2_g, ln2_b);

    // MLP
    dim3 g1(HIDh / 128, Mm / 128);
    gemm_fp16<1><<<g1, 128, GSMEM>>>(b_in, nullptr, nullptr, nullptr, HIDh, Dd);

    dim3 g2(Dd / 128, Mm / 128);
    gemm_fp16<2><<<g2, 128, GSMEM>>>(b_out, nullptr, nullptr, out, Dd, HIDh);
}

// round 17
// speedup vs baseline: 1.1399x; 1.0207x over previous
#include <cuda_runtime.h>
#include <cuda_fp16.h>
#include <math.h>
#include <stdint.h>

#define Bb   8
#define Ss   1024
#define Dd   768
#define Hh   12
#define HDd  64
#define HIDh 3072
#define Mm   (Bb*Ss)   // 8192

// ---------------- scratch (device globals; no allocs allowed) ----------------
__device__ __half g_q   [(size_t)Mm*Dd];
__device__ __half g_k   [(size_t)Mm*Dd];
__device__ __half g_v   [(size_t)Mm*Dd];
__device__ __half g_ln2 [(size_t)Mm*Dd];
__device__ __half g_h1  [(size_t)Mm*HIDh];
__device__ __half g_xc  [(size_t)Mm*Dd];
__device__ __half g_wq  [(size_t)Dd*Dd];      // [K,N] original layout, fp16
__device__ __half g_wk  [(size_t)Dd*Dd];
__device__ __half g_wv  [(size_t)Dd*Dd];
__device__ __half g_win [(size_t)Dd*HIDh];
__device__ __half g_wout[(size_t)HIDh*Dd];
__device__ __half g_ctxh[(size_t)Mm*Dd];      // fp16 attention output
__device__ float g_y  [(size_t)Mm*Dd];

__device__ __forceinline__ float gelu_exact(float x) {
    return 0.5f * x * (1.0f + erff(x * 0.70710678118654752f));
}
__device__ __forceinline__ void cp_async16(uint32_t saddr, const void* gaddr) {
    asm volatile("cp.async.cg.shared.global [%0], [%1], 16;\n" :: "r"(saddr), "l"(gaddr));
}
__device__ __forceinline__ uint32_t smem_u32(const void* p) {
    uint32_t a;
    asm("{ .reg .u64 t; cvta.to.shared.u64 t, %1; cvt.u32.u64 %0, t; }"
        : "=r"(a) : "l"(p));
    return a;
}
__device__ __forceinline__ void ldsm_x4(uint32_t& r0, uint32_t& r1,
                                        uint32_t& r2, uint32_t& r3, uint32_t a) {
    asm volatile("ldmatrix.sync.aligned.m8n8.x4.shared.b16 {%0,%1,%2,%3}, [%4];"
                 : "=r"(r0), "=r"(r1), "=r"(r2), "=r"(r3) : "r"(a));
}
__device__ __forceinline__ void ldsm_x4_t(uint32_t& r0, uint32_t& r1,
                                          uint32_t& r2, uint32_t& r3, uint32_t a) {
    asm volatile("ldmatrix.sync.aligned.m8n8.x4.trans.shared.b16 {%0,%1,%2,%3}, [%4];"
                 : "=r"(r0), "=r"(r1), "=r"(r2), "=r"(r3) : "r"(a));
}
__device__ __forceinline__ void mma_f16(float* c, const uint32_t* a,
                                        uint32_t b0, uint32_t b1) {
    asm volatile(
        "mma.sync.aligned.m16n8k16.row.col.f32.f16.f16.f32 "
        "{%0,%1,%2,%3},{%4,%5,%6,%7},{%8,%9},{%0,%1,%2,%3};"
        : "+f"(c[0]), "+f"(c[1]), "+f"(c[2]), "+f"(c[3])
        : "r"(a[0]), "r"(a[1]), "r"(a[2]), "r"(a[3]), "r"(b0), "r"(b1));
}
__device__ __forceinline__ uint32_t pack_h2(float a, float b) {
    __half2 h = __floats2half2_rn(a, b);
    return *(uint32_t*)&h;
}

// ---------------- prep kernels ----------------------------------------------
__global__ __launch_bounds__(256) void prep_x(const float* __restrict__ src, int n4)
{
    int i = blockIdx.x * 256 + threadIdx.x;
    if (i < n4) {
        float4 f = ((const float4*)src)[i];
        uint2 u;
        u.x = pack_h2(f.x, f.y);
        u.y = pack_h2(f.z, f.w);
        ((uint2*)g_xc)[i] = u;
    }
}

// one launch, z = 0..4 : wq wk wv win wout
__global__ __launch_bounds__(256) void prep_w5(const float* __restrict__ s0,
                                               const float* __restrict__ s1,
                                               const float* __restrict__ s2,
                                               const float* __restrict__ s3,
                                               const float* __restrict__ s4)
{
    const int id = blockIdx.z;
    const float* src = id == 0 ? s0 : id == 1 ? s1 : id == 2 ? s2
                     : id == 3 ? s3 : s4;
    __half* dst = id == 0 ? g_wq : id == 1 ? g_wk : id == 2 ? g_wv
                : id == 3 ? g_win : g_wout;
    const int n4 = (id < 3) ? (Dd*Dd/4) : (Dd*HIDh/4);
    int i = blockIdx.x * 256 + threadIdx.x;
    if (i < n4) {
        float4 f = ((const float4*)src)[i];
        uint2 u;
        u.x = pack_h2(f.x, f.y);
        u.y = pack_h2(f.z, f.w);
        ((uint2*)dst)[i] = u;
    }
}

// =====================================================================
// FP16 GEMM v7 (validated): CTA 128x128, 4 warps (2x2), warp 64x64,
// BK=64, 2-stage double buffer, ONE barrier per k-tile.
// A [M,K] ldsm; B [K,N] ldsm.trans.
// =====================================================================
#define HSTR 72
#define BSTR 136
#define A_STG_B (128*HSTR*2)        // 18432
#define B_STG_B (64*BSTR*2)         // 17408
#define GSMEM (2*A_STG_B + 2*B_STG_B)  // 71680

template<int MODE>
__global__ __launch_bounds__(128) void gemm_fp16(
    const float* __restrict__ bias0, const float* __restrict__ bias1,
    const float* __restrict__ bias2, float* __restrict__ Cout,
    int N, int K)
{
    extern __shared__ __half smem[];
    const int which = (MODE == 0) ? blockIdx.z : 0;

    const __half* A = (MODE == 0) ? g_xc : (MODE == 1 ? g_ln2 : g_h1);
    const __half* Bw = (MODE == 0)
        ? (which == 0 ? g_wq : (which == 1 ? g_wk : g_wv))
        : (MODE == 1 ? g_win : g_wout);
    const float* bias = (MODE == 0)
        ? (which == 0 ? bias0 : (which == 1 ? bias1 : bias2)) : bias0;

    const int tid  = threadIdx.x;
    const int lane = tid & 31;
    const int warp = tid >> 5;
    const int warpM = warp & 1;
    const int warpN = warp >> 1;
    const int quad = lane >> 2;
    const int tkid = lane & 3;

    const int m0 = blockIdx.y * 128;
    const int n0 = blockIdx.x * 128;

    uint32_t sA = smem_u32(smem);
    uint32_t sB = sA + 2 * A_STG_B;

    auto load_tile = [&](int kt, int buf) {
        const int k0 = kt * 64;
        #pragma unroll
        for (int i = 0; i < 8; i++) {
            int idx = tid + i * 128;
            int row = idx >> 3;
            int c8  = (idx & 7) * 8;
            cp_async16(sA + buf * A_STG_B + (row * HSTR + c8) * 2,
                       A + (size_t)(m0 + row) * K + k0 + c8);
        }
        #pragma unroll
        for (int i = 0; i < 8; i++) {
            int idx = tid + i * 128;
            int row = idx >> 4;
            int c8  = (idx & 15) * 8;
            cp_async16(sB + buf * B_STG_B + (row * BSTR + c8) * 2,
                       Bw + (size_t)(k0 + row) * N + n0 + c8);
        }
        asm volatile("cp.async.commit_group;\n");
    };

    float acc[4][8][4];
    #pragma unroll
    for (int i = 0; i < 4; i++)
        #pragma unroll
        for (int j = 0; j < 8; j++)
            #pragma unroll
            for (int r = 0; r < 4; r++) acc[i][j][r] = 0.0f;

    const int KT = K / 64;

    load_tile(0, 0);
    asm volatile("cp.async.wait_group 0;\n");
    __syncthreads();

    const int a_r = lane & 15;
    const int a_c = (lane >> 4) * 8;
    const int b_tr = (((lane >> 3) & 1) * 8) + (lane & 7);
    const int b_tc = (lane >> 4) * 8;

    for (int kt = 0; kt < KT; kt++) {
        const int buf = kt & 1;
        const uint32_t aB = sA + buf * A_STG_B;
        const uint32_t bB = sB + buf * B_STG_B;

        if (kt + 1 < KT) load_tile(kt + 1, buf ^ 1);

        #pragma unroll
        for (int ks = 0; ks < 4; ks++) {
            const int kb = ks * 16;
            uint32_t af[4][4];
            #pragma unroll
            for (int tm = 0; tm < 4; tm++) {
                uint32_t addr = aB +
                    ((warpM * 64 + tm * 16 + a_r) * HSTR + kb + a_c) * 2;
                ldsm_x4(af[tm][0], af[tm][1], af[tm][2], af[tm][3], addr);
            }
            uint32_t bf[8][2];
            #pragma unroll
            for (int p = 0; p < 4; p++) {
                uint32_t addr = bB +
                    ((kb + b_tr) * BSTR + warpN * 64 + p * 16 + b_tc) * 2;
                ldsm_x4_t(bf[2*p][0], bf[2*p][1], bf[2*p+1][0], bf[2*p+1][1], addr);
            }
            #pragma unroll
            for (int tm = 0; tm < 4; tm++)
                #pragma unroll
                for (int tn = 0; tn < 8; tn++)
                    mma_f16(acc[tm][tn], af[tm], bf[tn][0], bf[tn][1]);
        }

        if (kt + 1 < KT) {
            asm volatile("cp.async.wait_group 0;\n");
            __syncthreads();
        }
    }

    // ---------------- epilogue ----------------
    __half* qkv_out = (MODE == 0)
        ? (which == 0 ? g_q : (which == 1 ? g_k : g_v)) : nullptr;
    const float qscale = (MODE == 0 && which == 0) ? 0.125f : 1.0f;

    #pragma unroll
    for (int tm = 0; tm < 4; tm++) {
        #pragma unroll
        for (int tn = 0; tn < 8; tn++) {
            const int n = n0 + warpN * 64 + tn * 8 + tkid * 2;
            const float bn0 = bias[n], bn1 = bias[n + 1];
            #pragma unroll
            for (int half_m = 0; half_m < 2; half_m++) {
                const int m = m0 + warpM * 64 + tm * 16 + quad + half_m * 8;
                float v0 = acc[tm][tn][half_m * 2    ] + bn0;
                float v1 = acc[tm][tn][half_m * 2 + 1] + bn1;
                if (MODE == 0) {
                    int b = m >> 10, s = m & 1023;
                    int h = n >> 6, hd = n & 63;
                    uint32_t pk = pack_h2(v0 * qscale, v1 * qscale);
                    *(uint32_t*)&qkv_out[(((size_t)b * Hh + h) * Ss + s) * HDd + hd] = pk;
                } else if (MODE == 1) {
                    uint32_t pk = pack_h2(gelu_exact(v0), gelu_exact(v1));
                    *(uint32_t*)&g_h1[(size_t)m * N + n] = pk;
                } else {
                    const float* rp = g_y + (size_t)m * N + n;
                    float2 o = make_float2(gelu_exact(v0) + rp[0],
                                           gelu_exact(v1) + rp[1]);
                    *(float2*)&Cout[(size_t)m * N + n] = o;
                }
            }
        }
    }
}

// =====================================================================
// FP16 flash attention v4 (validated): block = 128 q rows, 4 warps x
// 32 rows, KV tile 64 rows, 2-buffer ring. Output fp16 (g_ctxh).
// =====================================================================
#define KSTRH 72
#define KVTILEH (64*KSTRH)
#define KVTILEB (KVTILEH*2)
#define ASMEM (4 * KVTILEB)

__global__ __launch_bounds__(128) void attn_tc(void)
{
    extern __shared__ __half asmem[];
    const int bh   = blockIdx.y;
    const int tid  = threadIdx.x;
    const int warp = tid >> 5;
    const int lane = tid & 31;
    const int quad = lane >> 2;
    const int tkid = lane & 3;

    const int q0 = blockIdx.x * 128 + warp * 32;
    const __half* kbase = g_k + (size_t)bh * Ss * HDd;
    const __half* vbase = g_v + (size_t)bh * Ss * HDd;

    uint32_t qf[2][4][4];
    #pragma unroll
    for (int mi = 0; mi < 2; mi++) {
        const __half* qb = g_q + ((size_t)bh * Ss + q0 + mi * 16) * HDd;
        #pragma unroll
        for (int kb = 0; kb < 4; kb++) {
            int c = kb * 16 + tkid * 2;
            qf[mi][kb][0] = *(const uint32_t*)&qb[(quad    ) * HDd + c    ];
            qf[mi][kb][1] = *(const uint32_t*)&qb[(quad + 8) * HDd + c    ];
            qf[mi][kb][2] = *(const uint32_t*)&qb[(quad    ) * HDd + c + 8];
            qf[mi][kb][3] = *(const uint32_t*)&qb[(quad + 8) * HDd + c + 8];
        }
    }

    float o[2][8][4];
    #pragma unroll
    for (int mi = 0; mi < 2; mi++)
        #pragma unroll
        for (int j = 0; j < 8; j++)
            #pragma unroll
            for (int r = 0; r < 4; r++) o[mi][j][r] = 0.0f;
    float mrow[2][2] = {{-1e30f, -1e30f}, {-1e30f, -1e30f}};
    float lrow[2][2] = {{0.0f, 0.0f}, {0.0f, 0.0f}};

    uint32_t sK = smem_u32(asmem);
    uint32_t sV = sK + 2 * KVTILEB;

    auto load_tile = [&](int t, int buf) {
        const __half* kp = kbase + (size_t)t * 64 * HDd;
        const __half* vp = vbase + (size_t)t * 64 * HDd;
        #pragma unroll
        for (int i = 0; i < 4; i++) {
            int idx = tid + i * 128;
            int row = idx >> 3;
            int c8  = (idx & 7) * 8;
            cp_async16(sK + buf * KVTILEB + (row * KSTRH + c8) * 2,
                       kp + row * HDd + c8);
            cp_async16(sV + buf * KVTILEB + (row * KSTRH + c8) * 2,
                       vp + row * HDd + c8);
        }
        asm volatile("cp.async.commit_group;\n");
    };

    const int NT = Ss / 64;
    load_tile(0, 0);
    asm volatile("cp.async.wait_group 0;\n");
    __syncthreads();

    const int kb_r = ((lane >> 4) * 8) + (lane & 7);
    const int kb_c = ((lane >> 3) & 1) * 8;
    const int vb_r = (((lane >> 3) & 1) * 8) + (lane & 7);
    const int vb_c = (lane >> 4) * 8;

    for (int t = 0; t < NT; t++) {
        const int buf = t & 1;
        const uint32_t kB = sK + buf * KVTILEB;
        const uint32_t vB = sV + buf * KVTILEB;

        if (t + 1 < NT) load_tile(t + 1, buf ^ 1);

        float sc[2][8][4];
        #pragma unroll
        for (int mi = 0; mi < 2; mi++)
            #pragma unroll
            for (int j = 0; j < 8; j++)
                #pragma unroll
                for (int r = 0; r < 4; r++) sc[mi][j][r] = 0.0f;

        #pragma unroll
        for (int kb = 0; kb < 4; kb++) {
            uint32_t bf[8][2];
            #pragma unroll
            for (int p = 0; p < 4; p++) {
                uint32_t addr = kB + ((p * 16 + kb_r) * KSTRH + kb * 16 + kb_c) * 2;
                ldsm_x4(bf[2*p][0], bf[2*p][1], bf[2*p+1][0], bf[2*p+1][1], addr);
            }
            #pragma unroll
            for (int j = 0; j < 8; j++) {
                mma_f16(sc[0][j], qf[0][kb], bf[j][0], bf[j][1]);
                mma_f16(sc[1][j], qf[1][kb], bf[j][0], bf[j][1]);
            }
        }

        #pragma unroll
        for (int mi = 0; mi < 2; mi++) {
            #pragma unroll
            for (int r = 0; r < 2; r++) {
                float tmax = -1e30f;
                #pragma unroll
                for (int j = 0; j < 8; j++)
                    tmax = fmaxf(tmax, fmaxf(sc[mi][j][2 * r], sc[mi][j][2 * r + 1]));
                tmax = fmaxf(tmax, __shfl_xor_sync(0xffffffffu, tmax, 1));
                tmax = fmaxf(tmax, __shfl_xor_sync(0xffffffffu, tmax, 2));

                float mnew = fmaxf(mrow[mi][r], tmax);
                float corr = __expf(mrow[mi][r] - mnew);
                mrow[mi][r] = mnew;
                lrow[mi][r] *= corr;
                #pragma unroll
                for (int j = 0; j < 8; j++) {
                    o[mi][j][2 * r]     *= corr;
                    o[mi][j][2 * r + 1] *= corr;
                }
            }
            #pragma unroll
            for (int j = 0; j < 8; j++) {
                sc[mi][j][0] = __expf(sc[mi][j][0] - mrow[mi][0]);
                sc[mi][j][1] = __expf(sc[mi][j][1] - mrow[mi][0]);
                sc[mi][j][2] = __expf(sc[mi][j][2] - mrow[mi][1]);
                sc[mi][j][3] = __expf(sc[mi][j][3] - mrow[mi][1]);
                lrow[mi][0] += sc[mi][j][0] + sc[mi][j][1];
                lrow[mi][1] += sc[mi][j][2] + sc[mi][j][3];
            }
        }

        #pragma unroll
        for (int th = 0; th < 4; th++) {
            uint32_t af[2][4];
            #pragma unroll
            for (int mi = 0; mi < 2; mi++) {
                af[mi][0] = pack_h2(sc[mi][2*th  ][0], sc[mi][2*th  ][1]);
                af[mi][1] = pack_h2(sc[mi][2*th  ][2], sc[mi][2*th  ][3]);
                af[mi][2] = pack_h2(sc[mi][2*th+1][0], sc[mi][2*th+1][1]);
                af[mi][3] = pack_h2(sc[mi][2*th+1][2], sc[mi][2*th+1][3]);
            }
            #pragma unroll
            for (int p = 0; p < 4; p++) {
                uint32_t vb[2][2];
                uint32_t addr = vB + ((th * 16 + vb_r) * KSTRH + p * 16 + vb_c) * 2;
                ldsm_x4_t(vb[0][0], vb[0][1], vb[1][0], vb[1][1], addr);
                #pragma unroll
                for (int mi = 0; mi < 2; mi++) {
                    mma_f16(o[mi][2*p  ], af[mi], vb[0][0], vb[0][1]);
                    mma_f16(o[mi][2*p+1], af[mi], vb[1][0], vb[1][1]);
                }
            }
        }

        if (t + 1 < NT) {
            asm volatile("cp.async.wait_group 0;\n");
            __syncthreads();
        }
    }

    #pragma unroll
    for (int mi = 0; mi < 2; mi++) {
        #pragma unroll
        for (int r = 0; r < 2; r++) {
            lrow[mi][r] += __shfl_xor_sync(0xffffffffu, lrow[mi][r], 1);
            lrow[mi][r] += __shfl_xor_sync(0xffffffffu, lrow[mi][r], 2);
        }
        float inv0 = 1.0f / lrow[mi][0];
        float inv1 = 1.0f / lrow[mi][1];

        __half* ob0 = g_ctxh + ((size_t)bh * Ss + q0 + mi * 16 + quad    ) * HDd;
        __half* ob1 = g_ctxh + ((size_t)bh * Ss + q0 + mi * 16 + quad + 8) * HDd;
        #pragma unroll
        for (int j = 0; j < 8; j++) {
            int col = j * 8 + tkid * 2;
            *(uint32_t*)&ob0[col] = pack_h2(o[mi][j][0] * inv0, o[mi][j][1] * inv0);
            *(uint32_t*)&ob1[col] = pack_h2(o[mi][j][2] * inv1, o[mi][j][3] * inv1);
        }
    }
}

// ---------------- fused LN1+LN2: warp-per-row, zero block barriers -----------
__global__ __launch_bounds__(256) void ln_fused(
    const float* __restrict__ x,
    const float* __restrict__ g1, const float* __restrict__ b1,
    const float* __restrict__ g2, const float* __restrict__ b2)
{
    const int warp = threadIdx.x >> 5;
    const int lane = threadIdx.x & 31;
    const int row  = blockIdx.x * 8 + warp;
    const int b = row >> 10, s = row & 1023;

    // phase 1: LN statistics of ctx row
    float cv[24];
    float sum = 0.0f, sq = 0.0f;
    #pragma unroll
    for (int i = 0; i < 24; i++) {
        int col = lane + i * 32;
        int h = col >> 6, hd = col & 63;
        float c = __half2float(g_ctxh[(((size_t)b * Hh + h) * Ss + s) * HDd + hd]);
        cv[i] = c;
        sum += c; sq += c * c;
    }
    #pragma unroll
    for (int o = 16; o > 0; o >>= 1) {
        sum += __shfl_xor_sync(0xffffffffu, sum, o);
        sq  += __shfl_xor_sync(0xffffffffu, sq,  o);
    }
    float mu = sum * (1.0f / Dd);
    float var = sq * (1.0f / Dd) - mu * mu;
    float rstd = rsqrtf(var + 1e-5f);

    // phase 2: y = x + LN1(ctx), stats of y
    float yv[24];
    float sum2 = 0.0f, sq2 = 0.0f;
    #pragma unroll
    for (int i = 0; i < 24; i++) {
        int col = lane + i * 32;
        float y = x[(size_t)row * Dd + col] +
                  (cv[i] - mu) * rstd * g1[col] + b1[col];
        yv[i] = y;
        sum2 += y; sq2 += y * y;
        g_y[(size_t)row * Dd + col] = y;
    }
    #pragma unroll
    for (int o = 16; o > 0; o >>= 1) {
        sum2 += __shfl_xor_sync(0xffffffffu, sum2, o);
        sq2  += __shfl_xor_sync(0xffffffffu, sq2,  o);
    }
    float mu2 = sum2 * (1.0f / Dd);
    float var2 = sq2 * (1.0f / Dd) - mu2 * mu2;
    float rstd2 = rsqrtf(var2 + 1e-5f);

    #pragma unroll
    for (int i = 0; i < 24; i++) {
        int col = lane + i * 32;
        g_ln2[(size_t)row * Dd + col] =
            __float2half_rn((yv[i] - mu2) * rstd2 * g2[col] + b2[col]);
    }
}

// ---------------- launch ----------------------------------------------------
extern "C" void kernel_launch(void* const* d_in, const int* in_sizes, int n_in,
                              void* d_out, int out_size)
{
    (void)in_sizes; (void)n_in; (void)out_size;
    const float* x     = (const float*)d_in[0];
    const float* wq    = (const float*)d_in[1];
    const float* bq    = (const float*)d_in[2];
    const float* wk    = (const float*)d_in[3];
    const float* bk    = (const float*)d_in[4];
    const float* wv    = (const float*)d_in[5];
    const float* bv    = (const float*)d_in[6];
    const float* ln1_g = (const float*)d_in[7];
    const float* ln1_b = (const float*)d_in[8];
    const float* ln2_g = (const float*)d_in[9];
    const float* ln2_b = (const float*)d_in[10];
    const float* w_in  = (const float*)d_in[11];
    const float* b_in  = (const float*)d_in[12];
    const float* w_out = (const float*)d_in[13];
    const float* b_out = (const float*)d_in[14];
    float* out = (float*)d_out;

    static int configured = 0;
    if (!configured) {
        cudaFuncSetAttribute(gemm_fp16<0>, cudaFuncAttributeMaxDynamicSharedMemorySize, GSMEM);
        cudaFuncSetAttribute(gemm_fp16<1>, cudaFuncAttributeMaxDynamicSharedMemorySize, GSMEM);
        cudaFuncSetAttribute(gemm_fp16<2>, cudaFuncAttributeMaxDynamicSharedMemorySize, GSMEM);
        cudaFuncSetAttribute(attn_tc, cudaFuncAttributeMaxDynamicSharedMemorySize, ASMEM);
        configured = 1;
    }

    // prep: fp32 -> fp16 at rest (no transpose; GEMM consumes [K,N] directly)
    prep_x<<<(Mm*Dd/4 + 255)/256, 256>>>(x, Mm*Dd/4);
    prep_w5<<<dim3((Dd*HIDh/4 + 255)/256, 1, 5), 256>>>(wq, wk, wv, w_in, w_out);

    // QKV projections (one launch, z = q/k/v)
    dim3 gq(Dd / 128, Mm / 128, 3);
    gemm_fp16<0><<<gq, 128, GSMEM>>>(bq, bk, bv, nullptr, Dd, Dd);

    // attention -> g_ctxh fp16
    dim3 ga(Ss / 128, Bb * Hh);
    attn_tc<<<ga, 128, ASMEM>>>();

    // fused LN1 + LN2 (warp-per-row)
    ln_fused<<<Mm / 8, 256>>>(x, ln1_g, ln1_b, ln2_g, ln2_b);

    // MLP
    dim3 g1(HIDh / 128, Mm / 128);
    gemm_fp16<1><<<g1, 128, GSMEM>>>(b_in, nullptr, nullptr, nullptr, HIDh, Dd);

    dim3 g2(Dd / 128, Mm / 128);
    gemm_fp16<2><<<g2, 128, GSMEM>>>(b_out, nullptr, nullptr, out, Dd, HIDh);
}